// round 14
// baseline (speedup 1.0000x reference)
#include <cuda_runtime.h>
#include <cuda_fp16.h>
#include <cstdint>

#define N_NODES   100000
#define N_EDGES   600000
#define D_FEAT    128
#define NOUT      128          // 64 (P = h@Wu^T + b) + 64 (Q = h@Wv^T)
#define GRIDX     148
#define TILES     782          // ceil(N_NODES / 128)

#define GBLK      64                    // edges per gather-CTA iteration
#define NBLKS     (N_EDGES / GBLK)      // 9375
#define GGRID     1036                  // 7 gather CTAs per SM

// ---------------------------------------------------------------------------
// Device scratch: per-node projections in fp16, stored SWIZZLED:
// byte for (node, col) = node*256 + ((col*2) ^ ((node & 7) << 4)).
// ---------------------------------------------------------------------------
__device__ __align__(256) __half g_PQh[(size_t)N_NODES * NOUT];

// Swizzled byte offset inside a [row][k] fp16 tile with 256B row stride.
__device__ __forceinline__ uint32_t tswz(int row, int kbyte) {
    return (uint32_t)(row * 256 + (kbyte ^ ((row & 7) << 4)));
}

__device__ __forceinline__ uint32_t smem_u32(const void* p) {
    uint32_t a;
    asm("{ .reg .u64 t; cvta.to.shared.u64 t, %1; cvt.u32.u64 %0, t; }" : "=r"(a) : "l"(p));
    return a;
}

__device__ __forceinline__ void ldsm_x4(uint32_t addr, uint32_t* r) {
    asm volatile("ldmatrix.sync.aligned.m8n8.x4.shared.b16 {%0,%1,%2,%3}, [%4];"
                 : "=r"(r[0]), "=r"(r[1]), "=r"(r[2]), "=r"(r[3]) : "r"(addr));
}
__device__ __forceinline__ void ldsm_x2(uint32_t addr, uint32_t* r) {
    asm volatile("ldmatrix.sync.aligned.m8n8.x2.shared.b16 {%0,%1}, [%2];"
                 : "=r"(r[0]), "=r"(r[1]) : "r"(addr));
}
__device__ __forceinline__ void mma_f16(float* c, const uint32_t* a, const uint32_t* b) {
    asm volatile("mma.sync.aligned.m16n8k16.row.col.f32.f16.f16.f32 "
                 "{%0,%1,%2,%3}, {%4,%5,%6,%7}, {%8,%9}, {%0,%1,%2,%3};"
                 : "+f"(c[0]), "+f"(c[1]), "+f"(c[2]), "+f"(c[3])
                 : "r"(a[0]), "r"(a[1]), "r"(a[2]), "r"(a[3]), "r"(b[0]), "r"(b[1]));
}

// Convert float4 -> 2x half2 and store 8B at swizzled offset.
__device__ __forceinline__ void f16_store(char* smem, uint32_t base,
                                          int row, int k4, float4 v) {
    __half2 h0 = __floats2half2_rn(v.x, v.y);
    __half2 h1 = __floats2half2_rn(v.z, v.w);
    uint32_t off = tswz(row, k4 * 8);
    *(uint2*)(smem + base + off) = make_uint2(*(uint32_t*)&h0, *(uint32_t*)&h1);
}

// ---------------------------------------------------------------------------
// GEMM smem: B once (fp16), A double-buffered (fp16). 96 KB, 1 CTA/SM.
// ---------------------------------------------------------------------------
#define SM_B     0u
#define SM_A0    32768u
#define SM_A1    65536u
#define SM_TOTAL 98304

// ---------------------------------------------------------------------------
// Kernel 1: persistent HMMA GEMM + bulk-store epilogue (R12 — unchanged;
// it is at the per-SM tensor-pipe floor).
// ---------------------------------------------------------------------------
__global__ void __launch_bounds__(256, 1)
gemm_kernel(const float* __restrict__ h, const float* __restrict__ W,
            const float* __restrict__ b) {
    extern __shared__ char smem[];
    const uint32_t sm_base = smem_u32(smem);
    const int tid = threadIdx.x;
    const int wid = tid >> 5;
    const int lid = tid & 31;

    // ---- Stage B once
    #pragma unroll
    for (int i = tid; i < 4096; i += 256) {
        int j  = i >> 5;
        int k4 = i & 31;
        const float* wp = (j < 64) ? &W[j * 256 + k4 * 4]
                                   : &W[(j - 64) * 256 + 128 + k4 * 4];
        f16_store(smem, SM_B, j, k4, *(const float4*)wp);
    }

    // ---- Stage A first tile into buf0
    {
        const int node0 = blockIdx.x * 128;
        #pragma unroll
        for (int i = 0; i < 16; ++i) {
            int idx = tid + i * 256;
            int m = idx >> 5, k4 = idx & 31;
            int gm = node0 + m; if (gm >= N_NODES) gm = N_NODES - 1;
            float4 v = *(const float4*)&h[(size_t)gm * D_FEAT + k4 * 4];
            f16_store(smem, SM_A0, m, k4, v);
        }
    }
    __syncthreads();

    const int wm = wid & 1;
    const int wn = wid >> 1;
    const int a_row = (lid & 7) + ((lid >> 3) & 1) * 8;
    const int a_kb  = (lid >> 4) * 16;
    const int b_row = (lid & 7);
    const int b_kb  = ((lid >> 3) & 1) * 16;
    const int xora  = (lid & 7) << 4;
    const int trow = lid >> 2;        // 0..7
    const int tcol = (lid & 3) * 2;

    float2 bias2[4];
    #pragma unroll
    for (int nf = 0; nf < 4; ++nf) {
        int col = wn * 32 + nf * 8 + tcol;
        bias2[nf] = (col < 64) ? *(const float2*)&b[col] : make_float2(0.f, 0.f);
    }

    int pb = 0;
    for (int t = blockIdx.x; t < TILES; t += GRIDX, pb ^= 1) {
        const int tn = t + GRIDX;
        const bool pre = (tn < TILES);

        if (!pre) asm volatile("griddepcontrol.launch_dependents;");

        // ---- (1) Prefetch next tile's h into registers
        float4 regs[16];
        if (pre) {
            const int node0n = tn * 128;
            #pragma unroll
            for (int i = 0; i < 16; ++i) {
                int idx = tid + i * 256;
                int m = idx >> 5, k4 = idx & 31;
                int gm = node0n + m; if (gm >= N_NODES) gm = N_NODES - 1;
                regs[i] = *(const float4*)&h[(size_t)gm * D_FEAT + k4 * 4];
            }
        }

        // ---- (2) MMA mainloop on buffer pb
        const uint32_t abase = sm_base + (pb ? SM_A1 : SM_A0);
        float acc[4][4][4];
        #pragma unroll
        for (int mf = 0; mf < 4; ++mf)
            #pragma unroll
            for (int nf = 0; nf < 4; ++nf)
                #pragma unroll
                for (int i = 0; i < 4; ++i) acc[mf][nf][i] = 0.0f;

        #pragma unroll
        for (int ks = 0; ks < 8; ++ks) {
            uint32_t af[4][4], bf[4][2];
            const uint32_t akoff = (uint32_t)((ks * 32 + a_kb) ^ xora);
            const uint32_t bkoff = (uint32_t)((ks * 32 + b_kb) ^ xora);
            #pragma unroll
            for (int mf = 0; mf < 4; ++mf) {
                uint32_t ro = (uint32_t)((wm * 64 + mf * 16 + a_row) * 256) + akoff;
                ldsm_x4(abase + ro, af[mf]);
            }
            #pragma unroll
            for (int nf = 0; nf < 4; ++nf) {
                uint32_t ro = (uint32_t)((wn * 32 + nf * 8 + b_row) * 256) + bkoff;
                ldsm_x2(sm_base + SM_B + ro, bf[nf]);
            }
            #pragma unroll
            for (int mf = 0; mf < 4; ++mf)
                #pragma unroll
                for (int nf = 0; nf < 4; ++nf)
                    mma_f16(acc[mf][nf], af[mf], bf[nf]);
        }

        // ---- (3) Drain previous bulk store, then sync
        if (tid == 0) asm volatile("cp.async.bulk.wait_group 0;" ::: "memory");
        __syncthreads();

        // ---- (4) Stage next A tile into buf[pb^1]
        if (pre) {
            const uint32_t obuf = pb ? SM_A0 : SM_A1;
            #pragma unroll
            for (int i = 0; i < 16; ++i) {
                int idx = tid + i * 256;
                int m = idx >> 5, k4 = idx & 31;
                f16_store(smem, obuf, m, k4, regs[i]);
            }
        }

        // ---- (5) Epilogue: bias + cvt, swizzled STS into dead buffer buf[pb]
        {
            char* pq = smem + (pb ? SM_A1 : SM_A0);
            const uint32_t key = (uint32_t)trow << 4;
            #pragma unroll
            for (int mf = 0; mf < 4; ++mf) {
                const int ra = wm * 64 + mf * 16 + trow;
                #pragma unroll
                for (int nf = 0; nf < 4; ++nf) {
                    const int col = wn * 32 + nf * 8 + tcol;
                    __half2 h0 = __floats2half2_rn(acc[mf][nf][0] + bias2[nf].x,
                                                   acc[mf][nf][1] + bias2[nf].y);
                    __half2 h1 = __floats2half2_rn(acc[mf][nf][2] + bias2[nf].x,
                                                   acc[mf][nf][3] + bias2[nf].y);
                    uint32_t co = ((uint32_t)(col * 2)) ^ key;
                    *(__half2*)(pq + ra * 256 + co)       = h0;
                    *(__half2*)(pq + (ra + 8) * 256 + co) = h1;
                }
            }
        }
        __syncthreads();

        // ---- (6) One bulk store: smem PQ tile -> g_PQh
        if (tid == 0) {
            const int node0 = t * 128;
            int rows = N_NODES - node0; if (rows > 128) rows = 128;
            asm volatile("fence.proxy.async.shared::cta;" ::: "memory");
            char* gdst = (char*)g_PQh + (size_t)node0 * 256;
            const uint32_t ssrc = sm_base + (pb ? SM_A1 : SM_A0);
            const uint32_t bytes = (uint32_t)rows * 256u;
            asm volatile("cp.async.bulk.global.shared::cta.bulk_group [%0], [%1], %2;"
                         :: "l"(gdst), "r"(ssrc), "r"(bytes) : "memory");
            asm volatile("cp.async.bulk.commit_group;" ::: "memory");
        }
    }

    if (tid == 0) asm volatile("cp.async.bulk.wait_group 0;" ::: "memory");
}

// ---------------------------------------------------------------------------
// Kernel 2: persistent gather. Per warp per 8 edges:
//   4 scalar idx LDG + 4 LDG.128 (lane (g,c): P/Q chunk c of edges eb+g,
//   eb+4+g — 8 lanes cover one full 128B row -> 4 lines per instr)
//   -> fp32 add -> STS into a 16 KB block stage -> one cp.async.bulk
//   per 64-edge block (double-buffered, wait_group 1).
// out[e][c] = P[src[e]][c] + Q[dst[e]][c]
// ---------------------------------------------------------------------------
__global__ void __launch_bounds__(256)
gather_kernel(const int* __restrict__ src, const int* __restrict__ dst,
              float* __restrict__ out) {
    __shared__ __align__(16) float stage[2][GBLK * 64];   // 2 x 16 KB

    const int tid  = threadIdx.x;
    const int w    = tid >> 5;
    const int lane = tid & 31;
    const int g    = lane >> 3;     // edge group 0..3
    const int c    = lane & 7;      // 16B chunk of the PQ half-row

    asm volatile("griddepcontrol.wait;" ::: "memory");

    const char* pqb = (const char*)g_PQh;
    const uint32_t cb = (uint32_t)c * 16u;
    int buf = 0;

    for (int blk = blockIdx.x; blk < NBLKS; blk += GGRID, buf ^= 1) {
        const int eb = blk * GBLK + w * 8;
        const int e0 = eb + g;
        const int e1 = eb + 4 + g;

        // Index loads (broadcast within 8-lane groups)
        unsigned s0 = (unsigned)__ldg(&src[e0]);
        unsigned s1 = (unsigned)__ldg(&src[e1]);
        unsigned d0 = (unsigned)__ldg(&dst[e0]);
        unsigned d1 = (unsigned)__ldg(&dst[e1]);
        if (s0 >= N_NODES) s0 = 0;
        if (s1 >= N_NODES) s1 = 0;
        if (d0 >= N_NODES) d0 = 0;
        if (d1 >= N_NODES) d1 = 0;

        // 4 coalesced LDG.128: P/Q chunk c of this thread's two edges.
        uint4 p0 = *(const uint4*)(pqb + (size_t)s0 * 256 +        (cb ^ ((s0 & 7u) << 4)));
        uint4 p1 = *(const uint4*)(pqb + (size_t)s1 * 256 +        (cb ^ ((s1 & 7u) << 4)));
        uint4 q0 = *(const uint4*)(pqb + (size_t)d0 * 256 + 128u + (cb ^ ((d0 & 7u) << 4)));
        uint4 q1 = *(const uint4*)(pqb + (size_t)d1 * 256 + 128u + (cb ^ ((d1 & 7u) << 4)));

        // Wait for the bulk store that last read stage[buf] (2 iters ago)
        if (tid == 0) asm volatile("cp.async.bulk.wait_group 1;" ::: "memory");
        __syncthreads();

        // Compute + stage: 8 fp32 per edge -> 2 float4 STS each.
        {
            float* sp = &stage[buf][(w * 8 + g) * 64 + c * 8];
            const __half2* ph = (const __half2*)&p0;
            const __half2* qh = (const __half2*)&q0;
            float4 lo, hi;
            float2 a, bb2;
            a = __half22float2(ph[0]); bb2 = __half22float2(qh[0]);
            lo.x = a.x + bb2.x; lo.y = a.y + bb2.y;
            a = __half22float2(ph[1]); bb2 = __half22float2(qh[1]);
            lo.z = a.x + bb2.x; lo.w = a.y + bb2.y;
            a = __half22float2(ph[2]); bb2 = __half22float2(qh[2]);
            hi.x = a.x + bb2.x; hi.y = a.y + bb2.y;
            a = __half22float2(ph[3]); bb2 = __half22float2(qh[3]);
            hi.z = a.x + bb2.x; hi.w = a.y + bb2.y;
            *(float4*)sp       = lo;
            *(float4*)(sp + 4) = hi;
        }
        {
            float* sp = &stage[buf][(w * 8 + 4 + g) * 64 + c * 8];
            const __half2* ph = (const __half2*)&p1;
            const __half2* qh = (const __half2*)&q1;
            float4 lo, hi;
            float2 a, bb2;
            a = __half22float2(ph[0]); bb2 = __half22float2(qh[0]);
            lo.x = a.x + bb2.x; lo.y = a.y + bb2.y;
            a = __half22float2(ph[1]); bb2 = __half22float2(qh[1]);
            lo.z = a.x + bb2.x; lo.w = a.y + bb2.y;
            a = __half22float2(ph[2]); bb2 = __half22float2(qh[2]);
            hi.x = a.x + bb2.x; hi.y = a.y + bb2.y;
            a = __half22float2(ph[3]); bb2 = __half22float2(qh[3]);
            hi.z = a.x + bb2.x; hi.w = a.y + bb2.y;
            *(float4*)sp       = lo;
            *(float4*)(sp + 4) = hi;
        }
        __syncthreads();

        // One bulk store: 16 KB contiguous block of out.
        if (tid == 0) {
            asm volatile("fence.proxy.async.shared::cta;" ::: "memory");
            float* gdst = out + (size_t)blk * GBLK * 64;
            const uint32_t ssrc = smem_u32(&stage[buf][0]);
            asm volatile("cp.async.bulk.global.shared::cta.bulk_group [%0], [%1], %2;"
                         :: "l"(gdst), "r"(ssrc), "n"(GBLK * 64 * 4) : "memory");
            asm volatile("cp.async.bulk.commit_group;" ::: "memory");
        }
    }

    if (tid == 0) asm volatile("cp.async.bulk.wait_group 0;" ::: "memory");
}

// ---------------------------------------------------------------------------
extern "C" void kernel_launch(void* const* d_in, const int* in_sizes, int n_in,
                              void* d_out, int out_size) {
    const float* h   = (const float*)d_in[0];
    const int*   src = (const int*)  d_in[1];
    const int*   dst = (const int*)  d_in[2];
    const float* W   = (const float*)d_in[3];
    const float* b   = (const float*)d_in[4];
    float* out = (float*)d_out;

    cudaFuncSetAttribute(gemm_kernel, cudaFuncAttributeMaxDynamicSharedMemorySize, SM_TOTAL);

    gemm_kernel<<<GRIDX, 256, SM_TOTAL>>>(h, W, b);

    cudaLaunchConfig_t cfg = {};
    cfg.gridDim  = dim3(GGRID);
    cfg.blockDim = dim3(256);
    cfg.dynamicSmemBytes = 0;
    cfg.stream = 0;
    cudaLaunchAttribute attr[1];
    attr[0].id = cudaLaunchAttributeProgrammaticStreamSerialization;
    attr[0].val.programmaticStreamSerializationAllowed = 1;
    cfg.attrs = attr;
    cfg.numAttrs = 1;
    cudaLaunchKernelEx(&cfg, gather_kernel, src, dst, out);
}

// round 15
// speedup vs baseline: 1.4433x; 1.4433x over previous
#include <cuda_runtime.h>
#include <cuda_fp16.h>
#include <cstdint>

#define N_NODES   100000
#define N_EDGES   600000
#define D_FEAT    128
#define NOUT      128          // 64 (P = h@Wu^T + b) + 64 (Q = h@Wv^T)
#define GRIDX     148
#define TILES     782          // ceil(N_NODES / 128)

// ---------------------------------------------------------------------------
// Device scratch: per-node projections in fp16, stored SWIZZLED:
// byte for (node, col) = node*256 + ((col*2) ^ ((node & 7) << 4)).
// ---------------------------------------------------------------------------
__device__ __align__(256) __half g_PQh[(size_t)N_NODES * NOUT];

// Swizzled byte offset inside a [row][k] fp16 tile with 256B row stride.
__device__ __forceinline__ uint32_t tswz(int row, int kbyte) {
    return (uint32_t)(row * 256 + (kbyte ^ ((row & 7) << 4)));
}

__device__ __forceinline__ uint32_t smem_u32(const void* p) {
    uint32_t a;
    asm("{ .reg .u64 t; cvta.to.shared.u64 t, %1; cvt.u32.u64 %0, t; }" : "=r"(a) : "l"(p));
    return a;
}

__device__ __forceinline__ void ldsm_x4(uint32_t addr, uint32_t* r) {
    asm volatile("ldmatrix.sync.aligned.m8n8.x4.shared.b16 {%0,%1,%2,%3}, [%4];"
                 : "=r"(r[0]), "=r"(r[1]), "=r"(r[2]), "=r"(r[3]) : "r"(addr));
}
__device__ __forceinline__ void ldsm_x2(uint32_t addr, uint32_t* r) {
    asm volatile("ldmatrix.sync.aligned.m8n8.x2.shared.b16 {%0,%1}, [%2];"
                 : "=r"(r[0]), "=r"(r[1]) : "r"(addr));
}
__device__ __forceinline__ void mma_f16(float* c, const uint32_t* a, const uint32_t* b) {
    asm volatile("mma.sync.aligned.m16n8k16.row.col.f32.f16.f16.f32 "
                 "{%0,%1,%2,%3}, {%4,%5,%6,%7}, {%8,%9}, {%0,%1,%2,%3};"
                 : "+f"(c[0]), "+f"(c[1]), "+f"(c[2]), "+f"(c[3])
                 : "r"(a[0]), "r"(a[1]), "r"(a[2]), "r"(a[3]), "r"(b[0]), "r"(b[1]));
}

// Convert float4 -> 2x half2 and store 8B at swizzled offset.
__device__ __forceinline__ void f16_store(char* smem, uint32_t base,
                                          int row, int k4, float4 v) {
    __half2 h0 = __floats2half2_rn(v.x, v.y);
    __half2 h1 = __floats2half2_rn(v.z, v.w);
    uint32_t off = tswz(row, k4 * 8);
    *(uint2*)(smem + base + off) = make_uint2(*(uint32_t*)&h0, *(uint32_t*)&h1);
}

// Convert two consecutive float4 -> 4x half2, single STS.128 (k4 must be even
// so the 16B destination chunk is swizzle-aligned).
__device__ __forceinline__ void f16_store2(char* smem, uint32_t base,
                                           int row, int k4, float4 v0, float4 v1) {
    __half2 a0 = __floats2half2_rn(v0.x, v0.y);
    __half2 a1 = __floats2half2_rn(v0.z, v0.w);
    __half2 a2 = __floats2half2_rn(v1.x, v1.y);
    __half2 a3 = __floats2half2_rn(v1.z, v1.w);
    uint32_t off = tswz(row, k4 * 8);
    *(uint4*)(smem + base + off) = make_uint4(*(uint32_t*)&a0, *(uint32_t*)&a1,
                                              *(uint32_t*)&a2, *(uint32_t*)&a3);
}

// ---------------------------------------------------------------------------
// GEMM smem: B once (fp16), A double-buffered (fp16). 96 KB, 1 CTA/SM.
// The dead MMA buffer doubles as the PQ epilogue staging tile (32 KB).
// ---------------------------------------------------------------------------
#define SM_B     0u
#define SM_A0    32768u
#define SM_A1    65536u
#define SM_TOTAL 98304

// ---------------------------------------------------------------------------
// Kernel 1: persistent HMMA GEMM + bulk-store epilogue (R12 structure;
// A staging now uses paired STS.128).
// ---------------------------------------------------------------------------
__global__ void __launch_bounds__(256, 1)
gemm_kernel(const float* __restrict__ h, const float* __restrict__ W,
            const float* __restrict__ b) {
    extern __shared__ char smem[];
    const uint32_t sm_base = smem_u32(smem);
    const int tid = threadIdx.x;
    const int wid = tid >> 5;
    const int lid = tid & 31;

    // ---- Stage B once
    #pragma unroll
    for (int i = tid; i < 4096; i += 256) {
        int j  = i >> 5;
        int k4 = i & 31;
        const float* wp = (j < 64) ? &W[j * 256 + k4 * 4]
                                   : &W[(j - 64) * 256 + 128 + k4 * 4];
        f16_store(smem, SM_B, j, k4, *(const float4*)wp);
    }

    // ---- Stage A first tile into buf0 (paired STS.128)
    {
        const int node0 = blockIdx.x * 128;
        #pragma unroll
        for (int i = 0; i < 8; ++i) {
            int p  = tid + i * 256;        // pair index 0..2047
            int m  = p >> 4;               // 0..127
            int k4 = (p & 15) * 2;         // even
            int gm = node0 + m; if (gm >= N_NODES) gm = N_NODES - 1;
            const float4* hp = (const float4*)&h[(size_t)gm * D_FEAT + k4 * 4];
            f16_store2(smem, SM_A0, m, k4, hp[0], hp[1]);
        }
    }
    __syncthreads();

    const int wm = wid & 1;
    const int wn = wid >> 1;
    const int a_row = (lid & 7) + ((lid >> 3) & 1) * 8;
    const int a_kb  = (lid >> 4) * 16;
    const int b_row = (lid & 7);
    const int b_kb  = ((lid >> 3) & 1) * 16;
    const int xora  = (lid & 7) << 4;
    const int trow = lid >> 2;        // 0..7
    const int tcol = (lid & 3) * 2;

    float2 bias2[4];
    #pragma unroll
    for (int nf = 0; nf < 4; ++nf) {
        int col = wn * 32 + nf * 8 + tcol;
        bias2[nf] = (col < 64) ? *(const float2*)&b[col] : make_float2(0.f, 0.f);
    }

    int pb = 0;
    for (int t = blockIdx.x; t < TILES; t += GRIDX, pb ^= 1) {
        const int tn = t + GRIDX;
        const bool pre = (tn < TILES);

        if (!pre) asm volatile("griddepcontrol.launch_dependents;");

        // ---- (1) Prefetch next tile's h into registers (8 float4-pairs)
        float4 regs[16];
        if (pre) {
            const int node0n = tn * 128;
            #pragma unroll
            for (int i = 0; i < 8; ++i) {
                int p  = tid + i * 256;
                int m  = p >> 4;
                int k4 = (p & 15) * 2;
                int gm = node0n + m; if (gm >= N_NODES) gm = N_NODES - 1;
                const float4* hp = (const float4*)&h[(size_t)gm * D_FEAT + k4 * 4];
                regs[i * 2]     = hp[0];
                regs[i * 2 + 1] = hp[1];
            }
        }

        // ---- (2) MMA mainloop on buffer pb
        const uint32_t abase = sm_base + (pb ? SM_A1 : SM_A0);
        float acc[4][4][4];
        #pragma unroll
        for (int mf = 0; mf < 4; ++mf)
            #pragma unroll
            for (int nf = 0; nf < 4; ++nf)
                #pragma unroll
                for (int i = 0; i < 4; ++i) acc[mf][nf][i] = 0.0f;

        #pragma unroll
        for (int ks = 0; ks < 8; ++ks) {
            uint32_t af[4][4], bf[4][2];
            const uint32_t akoff = (uint32_t)((ks * 32 + a_kb) ^ xora);
            const uint32_t bkoff = (uint32_t)((ks * 32 + b_kb) ^ xora);
            #pragma unroll
            for (int mf = 0; mf < 4; ++mf) {
                uint32_t ro = (uint32_t)((wm * 64 + mf * 16 + a_row) * 256) + akoff;
                ldsm_x4(abase + ro, af[mf]);
            }
            #pragma unroll
            for (int nf = 0; nf < 4; ++nf) {
                uint32_t ro = (uint32_t)((wn * 32 + nf * 8 + b_row) * 256) + bkoff;
                ldsm_x2(sm_base + SM_B + ro, bf[nf]);
            }
            #pragma unroll
            for (int mf = 0; mf < 4; ++mf)
                #pragma unroll
                for (int nf = 0; nf < 4; ++nf)
                    mma_f16(acc[mf][nf], af[mf], bf[nf]);
        }

        // ---- (3) Drain previous bulk store, then sync
        if (tid == 0) asm volatile("cp.async.bulk.wait_group 0;" ::: "memory");
        __syncthreads();

        // ---- (4) Stage next A tile into buf[pb^1] (paired STS.128)
        if (pre) {
            char* obuf = smem + (pb ? SM_A0 : SM_A1);
            #pragma unroll
            for (int i = 0; i < 8; ++i) {
                int p  = tid + i * 256;
                int m  = p >> 4;
                int k4 = (p & 15) * 2;
                f16_store2(obuf, 0u, m, k4, regs[i * 2], regs[i * 2 + 1]);
            }
        }

        // ---- (5) Epilogue: bias + cvt, swizzled STS into dead buffer buf[pb]
        {
            char* pq = smem + (pb ? SM_A1 : SM_A0);
            const uint32_t key = (uint32_t)trow << 4;
            #pragma unroll
            for (int mf = 0; mf < 4; ++mf) {
                const int ra = wm * 64 + mf * 16 + trow;
                #pragma unroll
                for (int nf = 0; nf < 4; ++nf) {
                    const int col = wn * 32 + nf * 8 + tcol;
                    __half2 h0 = __floats2half2_rn(acc[mf][nf][0] + bias2[nf].x,
                                                   acc[mf][nf][1] + bias2[nf].y);
                    __half2 h1 = __floats2half2_rn(acc[mf][nf][2] + bias2[nf].x,
                                                   acc[mf][nf][3] + bias2[nf].y);
                    uint32_t co = ((uint32_t)(col * 2)) ^ key;
                    *(__half2*)(pq + ra * 256 + co)       = h0;
                    *(__half2*)(pq + (ra + 8) * 256 + co) = h1;
                }
            }
        }
        __syncthreads();

        // ---- (6) One bulk store: smem PQ tile -> g_PQh
        if (tid == 0) {
            const int node0 = t * 128;
            int rows = N_NODES - node0; if (rows > 128) rows = 128;
            asm volatile("fence.proxy.async.shared::cta;" ::: "memory");
            char* gdst = (char*)g_PQh + (size_t)node0 * 256;
            const uint32_t ssrc = sm_base + (pb ? SM_A1 : SM_A0);
            const uint32_t bytes = (uint32_t)rows * 256u;
            asm volatile("cp.async.bulk.global.shared::cta.bulk_group [%0], [%1], %2;"
                         :: "l"(gdst), "r"(ssrc), "r"(bytes) : "memory");
            asm volatile("cp.async.bulk.commit_group;" ::: "memory");
        }
    }

    if (tid == 0) asm volatile("cp.async.bulk.wait_group 0;" ::: "memory");
}

// ---------------------------------------------------------------------------
// Kernel 2: gather-add, coalesced-store mapping (R13 — DRAM-write-bound).
// Warp covers 8 consecutive edges. Thread (p = lane>>4, c = lane&15) owns
// out cols 4c..4c+3 (one 16B chunk) of edges eb..eb+3 (eb = warp*8 + 4p).
// No index clamps: indices are valid by construction (randint 0..N_NODES).
// out[e][c] = P[src[e]][c] + Q[dst[e]][c]
// ---------------------------------------------------------------------------
__global__ void __launch_bounds__(256)
gather_kernel(const int* __restrict__ src, const int* __restrict__ dst,
              float* __restrict__ out) {
    const int t    = blockIdx.x * 256 + threadIdx.x;
    const int lane = t & 31;
    const int c    = lane & 15;                       // 16B out chunk
    const int eb   = (t >> 5) * 8 + (lane >> 4) * 4;  // first of 4 edges

    // Prologue: index loads — independent of GEMM output (PDL overlap).
    int4 sv = __ldg((const int4*)&src[eb]);
    int4 dv = __ldg((const int4*)&dst[eb]);
    unsigned sa[4] = {(unsigned)sv.x, (unsigned)sv.y, (unsigned)sv.z, (unsigned)sv.w};
    unsigned da[4] = {(unsigned)dv.x, (unsigned)dv.y, (unsigned)dv.z, (unsigned)dv.w};

    asm volatile("griddepcontrol.wait;" ::: "memory");

    const char* pqb = (const char*)g_PQh;
    const uint32_t chi = (uint32_t)(c >> 1) << 4;   // 16B-chunk offset (pre-swizzle)
    const uint32_t clo = (uint32_t)(c & 1) * 8;     // 8B half within chunk

    // Issue all 8 PQ loads first (max MLP), then compute + store.
    uint2 pv[4], qv[4];
    #pragma unroll
    for (int k = 0; k < 4; ++k) {
        pv[k] = *(const uint2*)(pqb + (size_t)sa[k] * 256 +
                                ((chi ^ ((sa[k] & 7u) << 4)) + clo));
        qv[k] = *(const uint2*)(pqb + (size_t)da[k] * 256 + 128u +
                                ((chi ^ ((da[k] & 7u) << 4)) + clo));
    }

    #pragma unroll
    for (int k = 0; k < 4; ++k) {
        float2 a0 = __half22float2(*(__half2*)&pv[k].x);
        float2 a1 = __half22float2(*(__half2*)&pv[k].y);
        float2 b0 = __half22float2(*(__half2*)&qv[k].x);
        float2 b1 = __half22float2(*(__half2*)&qv[k].y);
        float4 o = make_float4(a0.x + b0.x, a0.y + b0.y, a1.x + b1.x, a1.y + b1.y);
        __stcs((float4*)((char*)out + (size_t)(eb + k) * 256 + (uint32_t)c * 16), o);
    }
}

// ---------------------------------------------------------------------------
extern "C" void kernel_launch(void* const* d_in, const int* in_sizes, int n_in,
                              void* d_out, int out_size) {
    const float* h   = (const float*)d_in[0];
    const int*   src = (const int*)  d_in[1];
    const int*   dst = (const int*)  d_in[2];
    const float* W   = (const float*)d_in[3];
    const float* b   = (const float*)d_in[4];
    float* out = (float*)d_out;

    cudaFuncSetAttribute(gemm_kernel, cudaFuncAttributeMaxDynamicSharedMemorySize, SM_TOTAL);

    gemm_kernel<<<GRIDX, 256, SM_TOTAL>>>(h, W, b);

    // 75000 warps x 8 edges = 600000 edges; grid exact, no tail.
    const int gthreads = (N_EDGES / 8) * 32;   // 2.4M
    cudaLaunchConfig_t cfg = {};
    cfg.gridDim  = dim3(gthreads / 256);       // 9375
    cfg.blockDim = dim3(256);
    cfg.dynamicSmemBytes = 0;
    cfg.stream = 0;
    cudaLaunchAttribute attr[1];
    attr[0].id = cudaLaunchAttributeProgrammaticStreamSerialization;
    attr[0].val.programmaticStreamSerializationAllowed = 1;
    cfg.attrs = attr;
    cfg.numAttrs = 1;
    cudaLaunchKernelEx(&cfg, gather_kernel, src, dst, out);
}